// round 4
// baseline (speedup 1.0000x reference)
#include <cuda_runtime.h>
#include <cuda_bf16.h>
#include <math.h>

// Problem constants (fixed by the dataset)
#define BATCH 8
#define SEQ   2048
#define HDIM  4096
#define DDIM  128
#define NSENT 128

#define KSPLIT 16
#define KCH (HDIM / KSPLIT)   // 256 k per split block
#define KC  16                 // k-chunk staged in smem
#define NSTEP (KCH / KC)       // 16 stages

// ---------------- scratch (no allocations allowed) ----------------
__device__ int   g_idx[BATCH * NSENT];
__device__ float g_q  [BATCH * DDIM];
__device__ float g_v  [BATCH * NSENT];
__device__ float g_part[(size_t)KSPLIT * BATCH * NSENT * DDIM]; // 8 MB
__device__ float g_kf [(size_t)BATCH * NSENT * DDIM];           // 512 KB

// ---------------- packed f32x2 helpers ----------------
typedef unsigned long long f2_t;

__device__ __forceinline__ f2_t pk2(float lo, float hi) {
    f2_t r;
    asm("mov.b64 %0, {%1, %2};" : "=l"(r)
        : "r"(__float_as_uint(lo)), "r"(__float_as_uint(hi)));
    return r;
}
__device__ __forceinline__ void upk2(f2_t v, float& lo, float& hi) {
    unsigned a, b;
    asm("mov.b64 {%0, %1}, %2;" : "=r"(a), "=r"(b) : "l"(v));
    lo = __uint_as_float(a); hi = __uint_as_float(b);
}
__device__ __forceinline__ f2_t fma2(f2_t a, f2_t b, f2_t c) {
    f2_t d;
    asm("fma.rn.f32x2 %0, %1, %2, %3;" : "=l"(d) : "l"(a), "l"(b), "l"(c));
    return d;
}

// ---------------- kernel 1: extract sentence positions ----------------
__global__ void idx_kernel(const int* __restrict__ mask) {
    int b = blockIdx.x;
    int lane = threadIdx.x;            // 32 threads
    const int* row = mask + (size_t)b * SEQ;
    int count = 0;
    for (int c = 0; c < SEQ; c += 32) {
        int m = row[c + lane];
        unsigned bal = __ballot_sync(0xffffffffu, m != 0);
        if (m) {
            int pre = __popc(bal & ((1u << lane) - 1u));
            int slot = count + pre;
            if (slot < NSENT) g_idx[b * NSENT + slot] = c + lane;
        }
        count += __popc(bal);
    }
}

// ---------------- kernel 2: q_last GEMV + v GEMV (warp per output) ----
__global__ __launch_bounds__(128) void qv_kernel(
    const float* __restrict__ hidden,
    const float* __restrict__ Wq, const float* __restrict__ bq,
    const float* __restrict__ Wr, const float* __restrict__ br)
{
    int warp = threadIdx.x >> 5, lane = threadIdx.x & 31;
    int task = blockIdx.x * 4 + warp;          // 0..2047
    const float4* x4;
    const float4* w4;
    if (task < BATCH * DDIM) {                  // q task
        int b = task >> 7, d = task & 127;
        int row = g_idx[b * NSENT + NSENT - 1];
        x4 = (const float4*)(hidden + ((size_t)b * SEQ + row) * HDIM);
        w4 = (const float4*)(Wq + (size_t)d * HDIM);
    } else {                                    // v task
        int tt = task - BATCH * DDIM;
        int b = tt >> 7, i = tt & 127;
        int row = g_idx[b * NSENT + i];
        x4 = (const float4*)(hidden + ((size_t)b * SEQ + row) * HDIM);
        w4 = (const float4*)Wr;
    }
    float s = 0.f;
#pragma unroll 4
    for (int it = 0; it < HDIM / 4 / 32; it++) {
        float4 xa = x4[it * 32 + lane];
        float4 wa = w4[it * 32 + lane];
        s += xa.x * wa.x + xa.y * wa.y + xa.z * wa.z + xa.w * wa.w;
    }
#pragma unroll
    for (int o = 16; o > 0; o >>= 1) s += __shfl_xor_sync(0xffffffffu, s, o);
    if (lane == 0) {
        if (task < BATCH * DDIM) g_q[task] = s + bq[task & 127];
        else                     g_v[task - BATCH * DDIM] = s + br[0];
    }
}

// ---------------- kernel 3: K projection GEMM (split-K, f32x2) -------
// grid (KSPLIT, BATCH), 256 threads.
// Block tile: M=128 (sentences) x N=128 (d) x KCH. Thread tile 8x8.
__global__ __launch_bounds__(256, 1) void kgemm_kernel(
    const float* __restrict__ hidden, const float* __restrict__ Wk)
{
    __shared__ float4 Abuf[2][KC * 32];   // [kc][128] floats, k-major
    __shared__ float4 Wbuf[2][KC * 32];
    __shared__ int idx_sh[NSENT];

    int t  = threadIdx.x;
    int b  = blockIdx.y;
    int sp = blockIdx.x;

    if (t < NSENT) idx_sh[t] = g_idx[b * NSENT + t];
    __syncthreads();

    int m  = t & 127;          // row handled by this thread for staging
    int kq = t >> 7;           // 0 or 1 -> k-quads {kq, kq+2}
    const float4* pa = (const float4*)(hidden + ((size_t)b * SEQ + idx_sh[m]) * HDIM);
    const float4* pw = (const float4*)(Wk + (size_t)m * HDIM);
    int kb4 = sp * (KCH / 4);  // float4 base for this split

    int tx = t & 15;           // n group: n = tx*4 and 64+tx*4
    int ty = t >> 4;           // m group: m = ty*4 and 64+ty*4

    f2_t acc[8][4];
#pragma unroll
    for (int i = 0; i < 8; i++)
#pragma unroll
        for (int j = 0; j < 4; j++) acc[i][j] = 0ull;

    // prologue: stage 0
    float4 a0 = pa[kb4 + kq],     a1 = pa[kb4 + kq + 2];
    float4 w0 = pw[kb4 + kq],     w1 = pw[kb4 + kq + 2];
    {
        float* Af = (float*)Abuf[0];
        float* Wf = (float*)Wbuf[0];
        int k0 = kq * 4, k2 = (kq + 2) * 4;
        Af[(k0+0)*128+m]=a0.x; Af[(k0+1)*128+m]=a0.y; Af[(k0+2)*128+m]=a0.z; Af[(k0+3)*128+m]=a0.w;
        Af[(k2+0)*128+m]=a1.x; Af[(k2+1)*128+m]=a1.y; Af[(k2+2)*128+m]=a1.z; Af[(k2+3)*128+m]=a1.w;
        Wf[(k0+0)*128+m]=w0.x; Wf[(k0+1)*128+m]=w0.y; Wf[(k0+2)*128+m]=w0.z; Wf[(k0+3)*128+m]=w0.w;
        Wf[(k2+0)*128+m]=w1.x; Wf[(k2+1)*128+m]=w1.y; Wf[(k2+2)*128+m]=w1.z; Wf[(k2+3)*128+m]=w1.w;
    }
    __syncthreads();

    for (int s = 0; s < NSTEP; s++) {
        int cur = s & 1;
        if (s + 1 < NSTEP) {
            int kb = kb4 + (s + 1) * (KC / 4);
            a0 = pa[kb + kq]; a1 = pa[kb + kq + 2];
            w0 = pw[kb + kq]; w1 = pw[kb + kq + 2];
        }
        const float4* A4 = Abuf[cur];
        const float4* W4 = Wbuf[cur];
#pragma unroll
        for (int k = 0; k < KC; k++) {
            float4 av0 = A4[k * 32 + ty];
            float4 av1 = A4[k * 32 + 16 + ty];
            float4 wv0 = W4[k * 32 + tx];
            float4 wv1 = W4[k * 32 + 16 + tx];
            f2_t wp0 = pk2(wv0.x, wv0.y), wp1 = pk2(wv0.z, wv0.w);
            f2_t wp2 = pk2(wv1.x, wv1.y), wp3 = pk2(wv1.z, wv1.w);
            float am[8] = {av0.x, av0.y, av0.z, av0.w, av1.x, av1.y, av1.z, av1.w};
#pragma unroll
            for (int mi = 0; mi < 8; mi++) {
                f2_t aa = pk2(am[mi], am[mi]);
                acc[mi][0] = fma2(aa, wp0, acc[mi][0]);
                acc[mi][1] = fma2(aa, wp1, acc[mi][1]);
                acc[mi][2] = fma2(aa, wp2, acc[mi][2]);
                acc[mi][3] = fma2(aa, wp3, acc[mi][3]);
            }
        }
        if (s + 1 < NSTEP) {
            float* Af = (float*)Abuf[cur ^ 1];
            float* Wf = (float*)Wbuf[cur ^ 1];
            int k0 = kq * 4, k2 = (kq + 2) * 4;
            Af[(k0+0)*128+m]=a0.x; Af[(k0+1)*128+m]=a0.y; Af[(k0+2)*128+m]=a0.z; Af[(k0+3)*128+m]=a0.w;
            Af[(k2+0)*128+m]=a1.x; Af[(k2+1)*128+m]=a1.y; Af[(k2+2)*128+m]=a1.z; Af[(k2+3)*128+m]=a1.w;
            Wf[(k0+0)*128+m]=w0.x; Wf[(k0+1)*128+m]=w0.y; Wf[(k0+2)*128+m]=w0.z; Wf[(k0+3)*128+m]=w0.w;
            Wf[(k2+0)*128+m]=w1.x; Wf[(k2+1)*128+m]=w1.y; Wf[(k2+2)*128+m]=w1.z; Wf[(k2+3)*128+m]=w1.w;
        }
        __syncthreads();
    }

    float* out = g_part + ((size_t)(sp * BATCH + b)) * NSENT * DDIM;
#pragma unroll
    for (int mi = 0; mi < 8; mi++) {
        int mm = (mi < 4) ? (ty * 4 + mi) : (64 + ty * 4 + (mi - 4));
        float4 v0, v1;
        upk2(acc[mi][0], v0.x, v0.y); upk2(acc[mi][1], v0.z, v0.w);
        upk2(acc[mi][2], v1.x, v1.y); upk2(acc[mi][3], v1.z, v1.w);
        *(float4*)(out + (size_t)mm * DDIM + tx * 4)      = v0;
        *(float4*)(out + (size_t)mm * DDIM + 64 + tx * 4) = v1;
    }
}

// ---------------- kernel 4: reduce split-K partials + bias ----------
__global__ void kred_kernel(const float* __restrict__ bk) {
    int lin = blockIdx.x * 256 + threadIdx.x;       // over BATCH*NSENT*DDIM
    if (lin >= BATCH * NSENT * DDIM) return;
    int d   = lin & 127;
    int off = lin & (NSENT * DDIM - 1);
    int b   = lin >> 14;
    float s = bk[d];
#pragma unroll
    for (int sp = 0; sp < KSPLIT; sp++)
        s += g_part[((size_t)(sp * BATCH + b) << 14) + off];
    g_kf[lin] = s;
}

// ---------------- kernel 5: RoPE + attention + rewards --------------
__global__ __launch_bounds__(128) void finalize_kernel(float* __restrict__ out) {
    __shared__ float qsh[DDIM];
    __shared__ float red[NSENT];
    int b = blockIdx.x, t = threadIdx.x;

    const double LN1E4   = 9.210340371976184;      // ln(10000)
    const double INV_2PI = 0.15915494309189535;
    const double TWO_PI  = 6.283185307179586;

    // RoPE q at position NSENT-1
    if (t < DDIM / 2) {
        double f   = exp(-((double)(2 * t) / (double)DDIM) * LN1E4);
        double ang = (double)(NSENT - 1) * f;
        double kk  = rint(ang * INV_2PI);
        float  ar  = (float)(ang - kk * TWO_PI);
        float c, sn; sincosf(ar, &sn, &c);
        float re = g_q[b * DDIM + 2 * t], im = g_q[b * DDIM + 2 * t + 1];
        qsh[2 * t]     = re * c - im * sn;
        qsh[2 * t + 1] = re * sn + im * c;
    }
    __syncthreads();

    // logit_i = rope(k_i, pos=i) . rope(q, pos=127) / sqrt(D)
    const float* krow = g_kf + ((size_t)b << 14) + (size_t)t * DDIM;
    float logit = 0.f;
    double f = 1.0;
    const double r = exp(-LN1E4 / 64.0);           // theta^(-1/64)
    for (int j = 0; j < DDIM / 2; j++) {
        double ang = (double)t * f;
        double kk  = rint(ang * INV_2PI);
        float  ar  = (float)(ang - kk * TWO_PI);
        float c, sn; sincosf(ar, &sn, &c);
        float kr = krow[2 * j], ki = krow[2 * j + 1];
        logit += (kr * c - ki * sn) * qsh[2 * j] + (kr * sn + ki * c) * qsh[2 * j + 1];
        f *= r;
    }
    logit *= 0.08838834764831845f;                 // 1/sqrt(128)

    // softmax over the 128 sentences
    red[t] = logit; __syncthreads();
#pragma unroll
    for (int o = 64; o > 0; o >>= 1) { if (t < o) red[t] = fmaxf(red[t], red[t + o]); __syncthreads(); }
    float mx = red[0]; __syncthreads();
    float e = expf(logit - mx);
    red[t] = e; __syncthreads();
#pragma unroll
    for (int o = 64; o > 0; o >>= 1) { if (t < o) red[t] += red[t + o]; __syncthreads(); }
    float ssum = red[0]; __syncthreads();
    float attn = e / ssum;

    float v  = g_v[b * NSENT + t];
    float sr = (t == 0) ? v : (v - g_v[b * NSENT + t - 1]);
    float srw = sr * attn;
    out[b * NSENT + t] = srw;

    red[t] = srw; __syncthreads();
#pragma unroll
    for (int o = 64; o > 0; o >>= 1) { if (t < o) red[t] += red[t + o]; __syncthreads(); }
    if (t == 0) out[BATCH * NSENT + b] = red[0];
}

// ---------------- host launcher ----------------
extern "C" void kernel_launch(void* const* d_in, const int* in_sizes, int n_in,
                              void* d_out, int out_size) {
    const float* hidden = (const float*)d_in[0];
    const int*   mask   = (const int*)d_in[1];
    // num_sentences may or may not be materialized as an input (size-1 int)
    int off = (n_in > 2 && in_sizes[2] == 1) ? 3 : 2;
    const float* Wq = (const float*)d_in[off + 0];
    const float* bq = (const float*)d_in[off + 1];
    const float* Wk = (const float*)d_in[off + 2];
    const float* bk = (const float*)d_in[off + 3];
    const float* Wr = (const float*)d_in[off + 4];
    const float* br = (const float*)d_in[off + 5];
    float* out = (float*)d_out;

    idx_kernel<<<BATCH, 32>>>(mask);
    qv_kernel<<<(2 * BATCH * NSENT) / 4, 128>>>(hidden, Wq, bq, Wr, br);
    kgemm_kernel<<<dim3(KSPLIT, BATCH), 256>>>(hidden, Wk);
    kred_kernel<<<(BATCH * NSENT * DDIM + 255) / 256, 256>>>(bk);
    finalize_kernel<<<BATCH, 128>>>(out);
    (void)in_sizes; (void)n_in; (void)out_size;
}

// round 6
// speedup vs baseline: 1.2327x; 1.2327x over previous
#include <cuda_runtime.h>
#include <cuda_bf16.h>
#include <mma.h>
#include <math.h>
#include <cstdint>

using namespace nvcuda;

// Problem constants (fixed by the dataset)
#define BATCH 8
#define SEQ   2048
#define HDIM  4096
#define DDIM  128
#define NSENT 128

// split-K for the HMMA GEMM
#define KS2   16
#define KSL   (HDIM / KS2)     // 256 fp32 k per CTA
#define STG   64               // k per pipeline stage
#define NSTG  (KSL / STG)      // 4 stages

#define TSTRIDE 72             // bf16 tile row stride (144B, 16B-aligned, conflict-free)
#define TILE_BYTES (128 * TSTRIDE * 2)        // 18432
#define RAW_BYTES  (128 * STG * 4)            // 32768 per matrix
#define RAW_STAGE  (2 * RAW_BYTES)            // A + W = 65536
#define SM_TILES   (2 * RAW_STAGE)            // tiles start after 2 raw buffers
#define MMA_SMEM_TOTAL (SM_TILES + 4 * TILE_BYTES)  // 131072 + 73728 = 204800

// ---------------- scratch (no allocations allowed) ----------------
__device__ int   g_idx[BATCH * NSENT];
__device__ float g_q  [BATCH * DDIM];
__device__ float g_v  [BATCH * NSENT];
__device__ float g_part[(size_t)KS2 * BATCH * NSENT * DDIM]; // 8 MB fp32 partials
__device__ float g_kf [(size_t)BATCH * NSENT * DDIM];        // 512 KB

// ---------------- PTX helpers (baseline compute_103 only!) ----------------
__device__ __forceinline__ uint32_t smem_u32(const void* p) {
    uint32_t a;
    asm("{ .reg .u64 t; cvta.to.shared.u64 t, %1; cvt.u32.u64 %0, t; }" : "=r"(a) : "l"(p));
    return a;
}
__device__ __forceinline__ void cp_async16(uint32_t saddr, const void* g) {
    asm volatile("cp.async.cg.shared.global [%0], [%1], 16;" :: "r"(saddr), "l"(g));
}
#define CP_COMMIT() asm volatile("cp.async.commit_group;" ::: "memory")
#define CP_WAIT(n)  asm volatile("cp.async.wait_group %0;" :: "n"(n) : "memory")

// ---------------- kernel 1: extract sentence positions ----------------
__global__ void idx_kernel(const int* __restrict__ mask) {
    int b = blockIdx.x;
    int lane = threadIdx.x;            // 32 threads
    const int* row = mask + (size_t)b * SEQ;
    int count = 0;
    for (int c = 0; c < SEQ; c += 32) {
        int m = row[c + lane];
        unsigned bal = __ballot_sync(0xffffffffu, m != 0);
        if (m) {
            int pre = __popc(bal & ((1u << lane) - 1u));
            int slot = count + pre;
            if (slot < NSENT) g_idx[b * NSENT + slot] = c + lane;
        }
        count += __popc(bal);
    }
}

// ---------------- kernel 2: q_last GEMV + v GEMV (warp per output) ----
__global__ __launch_bounds__(128) void qv_kernel(
    const float* __restrict__ hidden,
    const float* __restrict__ Wq, const float* __restrict__ bq,
    const float* __restrict__ Wr, const float* __restrict__ br)
{
    int warp = threadIdx.x >> 5, lane = threadIdx.x & 31;
    int task = blockIdx.x * 4 + warp;          // 0..2047
    const float4* x4;
    const float4* w4;
    if (task < BATCH * DDIM) {                  // q task
        int b = task >> 7, d = task & 127;
        int row = g_idx[b * NSENT + NSENT - 1];
        x4 = (const float4*)(hidden + ((size_t)b * SEQ + row) * HDIM);
        w4 = (const float4*)(Wq + (size_t)d * HDIM);
    } else {                                    // v task
        int tt = task - BATCH * DDIM;
        int b = tt >> 7, i = tt & 127;
        int row = g_idx[b * NSENT + i];
        x4 = (const float4*)(hidden + ((size_t)b * SEQ + row) * HDIM);
        w4 = (const float4*)Wr;
    }
    float s = 0.f;
#pragma unroll 4
    for (int it = 0; it < HDIM / 4 / 32; it++) {
        float4 xa = x4[it * 32 + lane];
        float4 wa = w4[it * 32 + lane];
        s += xa.x * wa.x + xa.y * wa.y + xa.z * wa.z + xa.w * wa.w;
    }
#pragma unroll
    for (int o = 16; o > 0; o >>= 1) s += __shfl_xor_sync(0xffffffffu, s, o);
    if (lane == 0) {
        if (task < BATCH * DDIM) g_q[task] = s + bq[task & 127];
        else                     g_v[task - BATCH * DDIM] = s + br[0];
    }
}

// ---------------- kernel 3: K projection via WMMA bf16 (3-term split) ----
// grid (KS2, BATCH), 256 threads = 8 warps, each warp -> 64x32 output tile.
// smem: [2 x raw fp32 stage (A 32KB + W 32KB)] then [Ahi, Alo, Whi, Wlo] bf16
// tiles (128 x STG @ stride 72).
__global__ void __launch_bounds__(256, 1)
mma_kernel(const float* __restrict__ hidden, const float* __restrict__ Wk)
{
    extern __shared__ char smem[];
    __shared__ int idx_sh[NSENT];

    int t  = threadIdx.x;
    int sp = blockIdx.x, b = blockIdx.y;
    int wid = t >> 5;
    int warp_m = wid >> 2;     // 0..1 -> m base = warp_m*64
    int warp_n = wid & 3;      // 0..3 -> n base = warp_n*32

    if (t < NSENT) idx_sh[t] = g_idx[b * NSENT + t];
    __syncthreads();

    const int k0 = sp * KSL;

    __nv_bfloat16* Ahi = (__nv_bfloat16*)(smem + SM_TILES);
    __nv_bfloat16* Alo = (__nv_bfloat16*)(smem + SM_TILES + TILE_BYTES);
    __nv_bfloat16* Whi = (__nv_bfloat16*)(smem + SM_TILES + 2 * TILE_BYTES);
    __nv_bfloat16* Wlo = (__nv_bfloat16*)(smem + SM_TILES + 3 * TILE_BYTES);

    wmma::fragment<wmma::accumulator, 16, 16, 16, float> acc[4][2];
#pragma unroll
    for (int i = 0; i < 4; i++)
#pragma unroll
        for (int j = 0; j < 2; j++) wmma::fill_fragment(acc[i][j], 0.0f);

    // ---- issue stage 0 ----
    {
        float* rawA = (float*)smem;
        float* rawW = rawA + 8192;
#pragma unroll
        for (int i = 0; i < 8; i++) {
            int lin = t + 256 * i, row = lin >> 4, c4 = lin & 15;
            cp_async16(smem_u32(rawA + row * STG + c4 * 4),
                       hidden + ((size_t)b * SEQ + idx_sh[row]) * HDIM + k0 + c4 * 4);
        }
#pragma unroll
        for (int i = 0; i < 8; i++) {
            int lin = t + 256 * i, row = lin >> 4, c4 = lin & 15;
            cp_async16(smem_u32(rawW + row * STG + c4 * 4),
                       Wk + (size_t)row * HDIM + k0 + c4 * 4);
        }
        CP_COMMIT();
    }

    for (int s = 0; s < NSTG; s++) {
        // issue next stage while this one computes
        if (s + 1 < NSTG) {
            int kk = k0 + (s + 1) * STG;
            float* rawA = (float*)(smem + ((s + 1) & 1) * RAW_STAGE);
            float* rawW = rawA + 8192;
#pragma unroll
            for (int i = 0; i < 8; i++) {
                int lin = t + 256 * i, row = lin >> 4, c4 = lin & 15;
                cp_async16(smem_u32(rawA + row * STG + c4 * 4),
                           hidden + ((size_t)b * SEQ + idx_sh[row]) * HDIM + kk + c4 * 4);
            }
#pragma unroll
            for (int i = 0; i < 8; i++) {
                int lin = t + 256 * i, row = lin >> 4, c4 = lin & 15;
                cp_async16(smem_u32(rawW + row * STG + c4 * 4),
                           Wk + (size_t)row * HDIM + kk + c4 * 4);
            }
            CP_COMMIT();
            CP_WAIT(1);     // stage s raw data arrived
        } else {
            CP_WAIT(0);
        }
        __syncthreads();

        // ---- convert raw fp32 -> hi/lo bf16 tiles ----
        {
            const float4* rawA4 = (const float4*)(smem + (s & 1) * RAW_STAGE);
            const float4* rawW4 = rawA4 + 2048;
#pragma unroll
            for (int i = 0; i < 8; i++) {
                int lin = t + 256 * i, row = lin >> 4, c4 = lin & 15;
                float4 x = rawA4[row * 16 + c4];
                __nv_bfloat162 h0 = __floats2bfloat162_rn(x.x, x.y);
                __nv_bfloat162 h1 = __floats2bfloat162_rn(x.z, x.w);
                __nv_bfloat162 l0 = __floats2bfloat162_rn(x.x - __bfloat162float(h0.x),
                                                          x.y - __bfloat162float(h0.y));
                __nv_bfloat162 l1 = __floats2bfloat162_rn(x.z - __bfloat162float(h1.x),
                                                          x.w - __bfloat162float(h1.y));
                uint2 hv; hv.x = *(uint32_t*)&h0; hv.y = *(uint32_t*)&h1;
                uint2 lv; lv.x = *(uint32_t*)&l0; lv.y = *(uint32_t*)&l1;
                *(uint2*)(Ahi + row * TSTRIDE + c4 * 4) = hv;
                *(uint2*)(Alo + row * TSTRIDE + c4 * 4) = lv;
            }
#pragma unroll
            for (int i = 0; i < 8; i++) {
                int lin = t + 256 * i, row = lin >> 4, c4 = lin & 15;
                float4 x = rawW4[row * 16 + c4];
                __nv_bfloat162 h0 = __floats2bfloat162_rn(x.x, x.y);
                __nv_bfloat162 h1 = __floats2bfloat162_rn(x.z, x.w);
                __nv_bfloat162 l0 = __floats2bfloat162_rn(x.x - __bfloat162float(h0.x),
                                                          x.y - __bfloat162float(h0.y));
                __nv_bfloat162 l1 = __floats2bfloat162_rn(x.z - __bfloat162float(h1.x),
                                                          x.w - __bfloat162float(h1.y));
                uint2 hv; hv.x = *(uint32_t*)&h0; hv.y = *(uint32_t*)&h1;
                uint2 lv; lv.x = *(uint32_t*)&l0; lv.y = *(uint32_t*)&l1;
                *(uint2*)(Whi + row * TSTRIDE + c4 * 4) = hv;
                *(uint2*)(Wlo + row * TSTRIDE + c4 * 4) = lv;
            }
        }
        __syncthreads();

        // ---- compute: 3 product terms x 4 k16-steps ----
        const __nv_bfloat16* At[3] = {Ahi, Ahi, Alo};
        const __nv_bfloat16* Bt[3] = {Whi, Wlo, Whi};
#pragma unroll
        for (int term = 0; term < 3; term++) {
            const __nv_bfloat16* Ab = At[term] + warp_m * 64 * TSTRIDE;
            const __nv_bfloat16* Bb = Bt[term] + warp_n * 32 * TSTRIDE;
#pragma unroll
            for (int kk = 0; kk < STG / 16; kk++) {
                wmma::fragment<wmma::matrix_a, 16, 16, 16, __nv_bfloat16, wmma::row_major> af[4];
                wmma::fragment<wmma::matrix_b, 16, 16, 16, __nv_bfloat16, wmma::col_major> bf[2];
#pragma unroll
                for (int i = 0; i < 4; i++)
                    wmma::load_matrix_sync(af[i], Ab + i * 16 * TSTRIDE + kk * 16, TSTRIDE);
#pragma unroll
                for (int j = 0; j < 2; j++)
                    wmma::load_matrix_sync(bf[j], Bb + j * 16 * TSTRIDE + kk * 16, TSTRIDE);
#pragma unroll
                for (int i = 0; i < 4; i++)
#pragma unroll
                    for (int j = 0; j < 2; j++)
                        wmma::mma_sync(acc[i][j], af[i], bf[j], acc[i][j]);
            }
        }
        __syncthreads();   // tiles reused next stage
    }

    // ---- epilogue: store split-K partial ----
    float* out = g_part + (((size_t)(sp * BATCH + b)) << 14);
#pragma unroll
    for (int i = 0; i < 4; i++)
#pragma unroll
        for (int j = 0; j < 2; j++)
            wmma::store_matrix_sync(out + (size_t)(warp_m * 64 + i * 16) * DDIM
                                        + warp_n * 32 + j * 16,
                                    acc[i][j], DDIM, wmma::mem_row_major);
}

// ---------------- kernel 4: reduce split-K partials + bias (float4) ----
__global__ __launch_bounds__(256) void kred_kernel(const float* __restrict__ bk) {
    int lin = blockIdx.x * 256 + threadIdx.x;        // over B*NS*D/4 = 32768
    if (lin >= BATCH * NSENT * DDIM / 4) return;
    int b   = lin >> 12;                             // 4096 float4 per batch
    int off = lin & 4095;
    int d4  = lin & 31;
    float4 s = ((const float4*)bk)[d4];
#pragma unroll
    for (int sp = 0; sp < KS2; sp++) {
        float4 v = ((const float4*)g_part)[(((size_t)(sp * BATCH + b)) << 12) + off];
        s.x += v.x; s.y += v.y; s.z += v.z; s.w += v.w;
    }
    ((float4*)g_kf)[lin] = s;
}

// ---------------- kernel 5: RoPE + attention + rewards --------------
__global__ __launch_bounds__(128) void finalize_kernel(float* __restrict__ out) {
    __shared__ float qsh[DDIM];
    __shared__ float red[NSENT];
    int b = blockIdx.x, t = threadIdx.x;

    const double LN1E4   = 9.210340371976184;      // ln(10000)
    const double INV_2PI = 0.15915494309189535;
    const double TWO_PI  = 6.283185307179586;

    // RoPE q at position NSENT-1
    if (t < DDIM / 2) {
        double f   = exp(-((double)(2 * t) / (double)DDIM) * LN1E4);
        double ang = (double)(NSENT - 1) * f;
        double kk  = rint(ang * INV_2PI);
        float  ar  = (float)(ang - kk * TWO_PI);
        float c, sn; sincosf(ar, &sn, &c);
        float re = g_q[b * DDIM + 2 * t], im = g_q[b * DDIM + 2 * t + 1];
        qsh[2 * t]     = re * c - im * sn;
        qsh[2 * t + 1] = re * sn + im * c;
    }
    __syncthreads();

    // logit_i = rope(k_i, pos=i) . rope(q, pos=127) / sqrt(D)
    const float* krow = g_kf + ((size_t)b << 14) + (size_t)t * DDIM;
    float logit = 0.f;
    double f = 1.0;
    const double r = exp(-LN1E4 / 64.0);           // theta^(-1/64)
    for (int j = 0; j < DDIM / 2; j++) {
        double ang = (double)t * f;
        double kk  = rint(ang * INV_2PI);
        float  ar  = (float)(ang - kk * TWO_PI);
        float c, sn; sincosf(ar, &sn, &c);
        float kr = krow[2 * j], ki = krow[2 * j + 1];
        logit += (kr * c - ki * sn) * qsh[2 * j] + (kr * sn + ki * c) * qsh[2 * j + 1];
        f *= r;
    }
    logit *= 0.08838834764831845f;                 // 1/sqrt(128)

    // softmax over the 128 sentences
    red[t] = logit; __syncthreads();
#pragma unroll
    for (int o = 64; o > 0; o >>= 1) { if (t < o) red[t] = fmaxf(red[t], red[t + o]); __syncthreads(); }
    float mx = red[0]; __syncthreads();
    float e = expf(logit - mx);
    red[t] = e; __syncthreads();
#pragma unroll
    for (int o = 64; o > 0; o >>= 1) { if (t < o) red[t] += red[t + o]; __syncthreads(); }
    float ssum = red[0]; __syncthreads();
    float attn = e / ssum;

    float v  = g_v[b * NSENT + t];
    float sr = (t == 0) ? v : (v - g_v[b * NSENT + t - 1]);
    float srw = sr * attn;
    out[b * NSENT + t] = srw;

    red[t] = srw; __syncthreads();
#pragma unroll
    for (int o = 64; o > 0; o >>= 1) { if (t < o) red[t] += red[t + o]; __syncthreads(); }
    if (t == 0) out[BATCH * NSENT + b] = red[0];
}

// ---------------- host launcher ----------------
extern "C" void kernel_launch(void* const* d_in, const int* in_sizes, int n_in,
                              void* d_out, int out_size) {
    const float* hidden = (const float*)d_in[0];
    const int*   mask   = (const int*)d_in[1];
    int off = (n_in > 2 && in_sizes[2] == 1) ? 3 : 2;
    const float* Wq = (const float*)d_in[off + 0];
    const float* bq = (const float*)d_in[off + 1];
    const float* Wk = (const float*)d_in[off + 2];
    const float* bk = (const float*)d_in[off + 3];
    const float* Wr = (const float*)d_in[off + 4];
    const float* br = (const float*)d_in[off + 5];
    float* out = (float*)d_out;

    cudaFuncSetAttribute(mma_kernel, cudaFuncAttributeMaxDynamicSharedMemorySize,
                         MMA_SMEM_TOTAL);

    idx_kernel<<<BATCH, 32>>>(mask);
    mma_kernel<<<dim3(KS2, BATCH), 256, MMA_SMEM_TOTAL>>>(hidden, Wk);
    qv_kernel<<<(2 * BATCH * NSENT) / 4, 128>>>(hidden, Wq, bq, Wr, br);
    kred_kernel<<<(BATCH * NSENT * DDIM / 4 + 255) / 256, 256>>>(bk);
    finalize_kernel<<<BATCH, 128>>>(out);
    (void)in_sizes; (void)n_in; (void)out_size;
}

// round 7
// speedup vs baseline: 1.8710x; 1.5177x over previous
#include <cuda_runtime.h>
#include <cuda_bf16.h>
#include <mma.h>
#include <math.h>
#include <cstdint>

using namespace nvcuda;

// Problem constants (fixed by the dataset)
#define BATCH 8
#define SEQ   2048
#define HDIM  4096
#define DDIM  128
#define NSENT 128

// split-K for the HMMA GEMM
#define KS2   16
#define KSL   (HDIM / KS2)     // 256 fp32 k per CTA
#define STG   64               // k per pipeline stage
#define NSTG  (KSL / STG)      // 4 stages

#define TSTRIDE 72             // bf16 tile row stride (144B, 16B-aligned, conflict-free)
#define ATILE   (128 * TSTRIDE * 2)   // 18432 bytes per bf16 tile
#define RAWA_SZ (128 * STG * 4)       // 32768 bytes raw fp32 A stage
#define AT_OFF  (2 * RAWA_SZ)         // 65536 : A hi/lo tiles (single buffered)
#define WT_OFF  (AT_OFF + 2 * ATILE)  // 102400: W hi/lo tiles (double buffered)
#define MMA_SMEM_TOTAL (WT_OFF + 2 * 2 * ATILE)  // 176128 bytes

// ---------------- scratch (no allocations allowed) ----------------
__device__ int   g_idx[BATCH * NSENT];
__device__ float g_q  [BATCH * DDIM];
__device__ float g_v  [BATCH * NSENT];
__device__ float g_part[(size_t)KS2 * BATCH * NSENT * DDIM]; // 8 MB fp32 partials
__device__ float g_kf [(size_t)BATCH * NSENT * DDIM];        // 512 KB (RoPE'd K)
__device__ __nv_bfloat16 g_Whi[(size_t)DDIM * HDIM];         // 1 MB
__device__ __nv_bfloat16 g_Wlo[(size_t)DDIM * HDIM];         // 1 MB

// ---------------- PTX helpers (baseline compute_103 only!) ----------------
__device__ __forceinline__ uint32_t smem_u32(const void* p) {
    uint32_t a;
    asm("{ .reg .u64 t; cvta.to.shared.u64 t, %1; cvt.u32.u64 %0, t; }" : "=r"(a) : "l"(p));
    return a;
}
__device__ __forceinline__ void cp_async16(uint32_t saddr, const void* g) {
    asm volatile("cp.async.cg.shared.global [%0], [%1], 16;" :: "r"(saddr), "l"(g));
}
#define CP_COMMIT() asm volatile("cp.async.commit_group;" ::: "memory")
#define CP_WAIT(n)  asm volatile("cp.async.wait_group %0;" :: "n"(n) : "memory")

// ---------------- kernel 0: pre-split Wk into hi/lo bf16 ----------------
__global__ __launch_bounds__(256) void prepw_kernel(const float* __restrict__ Wk) {
    int i = blockIdx.x * 256 + threadIdx.x;       // over DDIM*HDIM/4 = 131072 float4
    if (i >= DDIM * HDIM / 4) return;
    float4 x = ((const float4*)Wk)[i];
    __nv_bfloat162 h0 = __floats2bfloat162_rn(x.x, x.y);
    __nv_bfloat162 h1 = __floats2bfloat162_rn(x.z, x.w);
    __nv_bfloat162 l0 = __floats2bfloat162_rn(x.x - __bfloat162float(h0.x),
                                              x.y - __bfloat162float(h0.y));
    __nv_bfloat162 l1 = __floats2bfloat162_rn(x.z - __bfloat162float(h1.x),
                                              x.w - __bfloat162float(h1.y));
    uint2 hv; hv.x = *(uint32_t*)&h0; hv.y = *(uint32_t*)&h1;
    uint2 lv; lv.x = *(uint32_t*)&l0; lv.y = *(uint32_t*)&l1;
    ((uint2*)g_Whi)[i] = hv;
    ((uint2*)g_Wlo)[i] = lv;
}

// ---------------- kernel 1: extract sentence positions (MLP-64) --------
__global__ void idx_kernel(const int* __restrict__ mask) {
    int b = blockIdx.x;
    int lane = threadIdx.x;            // 32 threads
    const int4* row = (const int4*)(mask + (size_t)b * SEQ);
    int4 v[16];
#pragma unroll
    for (int i = 0; i < 16; i++) v[i] = row[i * 32 + lane];   // all loads in flight
    unsigned lt = (1u << lane) - 1u;
    int count = 0;
#pragma unroll
    for (int i = 0; i < 16; i++) {
        unsigned b0 = __ballot_sync(0xffffffffu, v[i].x != 0);
        unsigned b1 = __ballot_sync(0xffffffffu, v[i].y != 0);
        unsigned b2 = __ballot_sync(0xffffffffu, v[i].z != 0);
        unsigned b3 = __ballot_sync(0xffffffffu, v[i].w != 0);
        int prel = __popc(b0 & lt) + __popc(b1 & lt) + __popc(b2 & lt) + __popc(b3 & lt);
        int basepos = i * 128 + lane * 4;
        int slot = count + prel;
        if (v[i].x) { if (slot < NSENT) g_idx[b * NSENT + slot] = basepos + 0; slot++; }
        if (v[i].y) { if (slot < NSENT) g_idx[b * NSENT + slot] = basepos + 1; slot++; }
        if (v[i].z) { if (slot < NSENT) g_idx[b * NSENT + slot] = basepos + 2; slot++; }
        if (v[i].w) { if (slot < NSENT) g_idx[b * NSENT + slot] = basepos + 3; slot++; }
        count += __popc(b0) + __popc(b1) + __popc(b2) + __popc(b3);
    }
}

// ---------------- kernel 2: q_last GEMV + v GEMV (warp per output) ----
__global__ __launch_bounds__(128) void qv_kernel(
    const float* __restrict__ hidden,
    const float* __restrict__ Wq, const float* __restrict__ bq,
    const float* __restrict__ Wr, const float* __restrict__ br)
{
    int warp = threadIdx.x >> 5, lane = threadIdx.x & 31;
    int task = blockIdx.x * 4 + warp;          // 0..2047
    const float4* x4;
    const float4* w4;
    if (task < BATCH * DDIM) {                  // q task
        int b = task >> 7, d = task & 127;
        int row = g_idx[b * NSENT + NSENT - 1];
        x4 = (const float4*)(hidden + ((size_t)b * SEQ + row) * HDIM);
        w4 = (const float4*)(Wq + (size_t)d * HDIM);
    } else {                                    // v task
        int tt = task - BATCH * DDIM;
        int b = tt >> 7, i = tt & 127;
        int row = g_idx[b * NSENT + i];
        x4 = (const float4*)(hidden + ((size_t)b * SEQ + row) * HDIM);
        w4 = (const float4*)Wr;
    }
    float s = 0.f;
#pragma unroll 4
    for (int it = 0; it < HDIM / 4 / 32; it++) {
        float4 xa = x4[it * 32 + lane];
        float4 wa = w4[it * 32 + lane];
        s += xa.x * wa.x + xa.y * wa.y + xa.z * wa.z + xa.w * wa.w;
    }
#pragma unroll
    for (int o = 16; o > 0; o >>= 1) s += __shfl_xor_sync(0xffffffffu, s, o);
    if (lane == 0) {
        if (task < BATCH * DDIM) g_q[task] = s + bq[task & 127];
        else                     g_v[task - BATCH * DDIM] = s + br[0];
    }
}

// ---------------- kernel 3: K projection via WMMA bf16 (3-term split) ----
// grid (KS2, BATCH), 256 threads = 8 warps, each warp -> 64x32 output tile.
// smem: 2x raw fp32 A stage | Ahi,Alo tiles | 2x (Whi,Wlo) tiles (from g_W*).
__global__ void __launch_bounds__(256, 1)
mma_kernel(const float* __restrict__ hidden)
{
    extern __shared__ char smem[];
    __shared__ int idx_sh[NSENT];

    int t  = threadIdx.x;
    int sp = blockIdx.x, b = blockIdx.y;
    int wid = t >> 5;
    int warp_m = wid >> 2;     // 0..1 -> m base = warp_m*64
    int warp_n = wid & 3;      // 0..3 -> n base = warp_n*32

    if (t < NSENT) idx_sh[t] = g_idx[b * NSENT + t];
    __syncthreads();

    const int k0 = sp * KSL;

    __nv_bfloat16* Ahi = (__nv_bfloat16*)(smem + AT_OFF);
    __nv_bfloat16* Alo = (__nv_bfloat16*)(smem + AT_OFF + ATILE);

    wmma::fragment<wmma::accumulator, 16, 16, 16, float> acc[4][2];
#pragma unroll
    for (int i = 0; i < 4; i++)
#pragma unroll
        for (int j = 0; j < 2; j++) wmma::fill_fragment(acc[i][j], 0.0f);

    // stage issue helper (A raw fp32 + W bf16 tiles direct)
    auto issue_stage = [&](int s) {
        int kk = k0 + s * STG;
        int buf = s & 1;
        float* rawA = (float*)(smem + buf * RAWA_SZ);
        char*  wt   = smem + WT_OFF + buf * 2 * ATILE;
#pragma unroll
        for (int i = 0; i < 8; i++) {             // A: 2048 float4 chunks
            int lin = t + 256 * i, row = lin >> 4, c4 = lin & 15;
            cp_async16(smem_u32(rawA + row * STG + c4 * 4),
                       hidden + ((size_t)b * SEQ + idx_sh[row]) * HDIM + kk + c4 * 4);
        }
#pragma unroll
        for (int i = 0; i < 8; i++) {             // W: 2048 16B chunks (hi then lo)
            int lin = t + 256 * i;
            int mat = lin >> 10;                  // 0=hi, 1=lo
            int rem = lin & 1023;
            int row = rem >> 3, ch = rem & 7;
            const __nv_bfloat16* src = (mat ? g_Wlo : g_Whi) + (size_t)row * HDIM + kk + ch * 8;
            cp_async16(smem_u32(wt + mat * ATILE + row * (TSTRIDE * 2) + ch * 16), src);
        }
        CP_COMMIT();
    };

    issue_stage(0);

    for (int s = 0; s < NSTG; s++) {
        if (s + 1 < NSTG) { issue_stage(s + 1); CP_WAIT(1); }
        else              { CP_WAIT(0); }
        __syncthreads();

        // ---- convert raw fp32 A -> hi/lo bf16 tiles ----
        {
            const float4* rawA4 = (const float4*)(smem + (s & 1) * RAWA_SZ);
#pragma unroll
            for (int i = 0; i < 8; i++) {
                int lin = t + 256 * i, row = lin >> 4, c4 = lin & 15;
                float4 x = rawA4[row * 16 + c4];
                __nv_bfloat162 h0 = __floats2bfloat162_rn(x.x, x.y);
                __nv_bfloat162 h1 = __floats2bfloat162_rn(x.z, x.w);
                __nv_bfloat162 l0 = __floats2bfloat162_rn(x.x - __bfloat162float(h0.x),
                                                          x.y - __bfloat162float(h0.y));
                __nv_bfloat162 l1 = __floats2bfloat162_rn(x.z - __bfloat162float(h1.x),
                                                          x.w - __bfloat162float(h1.y));
                uint2 hv; hv.x = *(uint32_t*)&h0; hv.y = *(uint32_t*)&h1;
                uint2 lv; lv.x = *(uint32_t*)&l0; lv.y = *(uint32_t*)&l1;
                *(uint2*)(Ahi + row * TSTRIDE + c4 * 4) = hv;
                *(uint2*)(Alo + row * TSTRIDE + c4 * 4) = lv;
            }
        }
        __syncthreads();

        // ---- compute: 3 product terms x 4 k16-steps ----
        __nv_bfloat16* Whi = (__nv_bfloat16*)(smem + WT_OFF + (s & 1) * 2 * ATILE);
        __nv_bfloat16* Wlo = (__nv_bfloat16*)((char*)Whi + ATILE);
        const __nv_bfloat16* At[3] = {Ahi, Ahi, Alo};
        const __nv_bfloat16* Bt[3] = {Whi, Wlo, Whi};
#pragma unroll
        for (int term = 0; term < 3; term++) {
            const __nv_bfloat16* Ab = At[term] + warp_m * 64 * TSTRIDE;
            const __nv_bfloat16* Bb = Bt[term] + warp_n * 32 * TSTRIDE;
#pragma unroll
            for (int kk = 0; kk < STG / 16; kk++) {
                wmma::fragment<wmma::matrix_a, 16, 16, 16, __nv_bfloat16, wmma::row_major> af[4];
                wmma::fragment<wmma::matrix_b, 16, 16, 16, __nv_bfloat16, wmma::col_major> bf[2];
#pragma unroll
                for (int i = 0; i < 4; i++)
                    wmma::load_matrix_sync(af[i], Ab + i * 16 * TSTRIDE + kk * 16, TSTRIDE);
#pragma unroll
                for (int j = 0; j < 2; j++)
                    wmma::load_matrix_sync(bf[j], Bb + j * 16 * TSTRIDE + kk * 16, TSTRIDE);
#pragma unroll
                for (int i = 0; i < 4; i++)
#pragma unroll
                    for (int j = 0; j < 2; j++)
                        wmma::mma_sync(acc[i][j], af[i], bf[j], acc[i][j]);
            }
        }
        __syncthreads();   // A tiles + W buf reused next stage
    }

    // ---- epilogue: store split-K partial ----
    float* out = g_part + (((size_t)(sp * BATCH + b)) << 14);
#pragma unroll
    for (int i = 0; i < 4; i++)
#pragma unroll
        for (int j = 0; j < 2; j++)
            wmma::store_matrix_sync(out + (size_t)(warp_m * 64 + i * 16) * DDIM
                                        + warp_n * 32 + j * 16,
                                    acc[i][j], DDIM, wmma::mem_row_major);
}

// ---------------- kernel 4: split-K reduce + bias + RoPE (float2) ----
__global__ __launch_bounds__(256) void kred_kernel(const float* __restrict__ bk) {
    int p = blockIdx.x * 256 + threadIdx.x;       // pair id over B*NS*64 = 65536
    if (p >= BATCH * NSENT * 64) return;
    int b = p >> 13;
    int t = (p >> 6) & 127;                        // sentence index
    int j = p & 63;                                // rotation pair
    int off2 = p & 8191;                           // (t*64 + j)
    float2 s = ((const float2*)bk)[j];
#pragma unroll
    for (int sp = 0; sp < KS2; sp++) {
        float2 v = ((const float2*)g_part)[(((size_t)(sp * BATCH + b)) << 13) + off2];
        s.x += v.x; s.y += v.y;
    }
    // RoPE at position t:  f = theta^(-j/64) = exp2(-j * log2(1e4)/64)
    float f = exp2f(-(float)j * 0.20762050593045163f);
    float ang = (float)t * f;
    float sn, cs; sincosf(ang, &sn, &cs);
    float2 o;
    o.x = s.x * cs - s.y * sn;
    o.y = s.x * sn + s.y * cs;
    ((float2*)g_kf)[p] = o;
}

// ---------------- kernel 5: attention + rewards ----------------------
__global__ __launch_bounds__(128) void finalize_kernel(float* __restrict__ out) {
    __shared__ float qsh[DDIM];
    __shared__ float red[NSENT];
    int b = blockIdx.x, t = threadIdx.x;

    const double LN1E4   = 9.210340371976184;      // ln(10000)
    const double INV_2PI = 0.15915494309189535;
    const double TWO_PI  = 6.283185307179586;

    // RoPE q at position NSENT-1, pre-scaled by 1/sqrt(D)
    if (t < DDIM / 2) {
        double f   = exp(-((double)(2 * t) / (double)DDIM) * LN1E4);
        double ang = (double)(NSENT - 1) * f;
        double kk  = rint(ang * INV_2PI);
        float  ar  = (float)(ang - kk * TWO_PI);
        float c, sn; sincosf(ar, &sn, &c);
        float re = g_q[b * DDIM + 2 * t], im = g_q[b * DDIM + 2 * t + 1];
        const float isd = 0.08838834764831845f;    // 1/sqrt(128)
        qsh[2 * t]     = (re * c - im * sn) * isd;
        qsh[2 * t + 1] = (re * sn + im * c) * isd;
    }
    __syncthreads();

    // logit_t = rope(k_t) . rope(q)/sqrt(D)  (k already rotated in kred)
    const float4* krow = (const float4*)(g_kf + ((size_t)b << 14) + (size_t)t * DDIM);
    const float4* q4   = (const float4*)qsh;
    float logit = 0.f;
#pragma unroll
    for (int j = 0; j < DDIM / 4; j++) {
        float4 k4 = krow[j], qq = q4[j];
        logit += k4.x * qq.x + k4.y * qq.y + k4.z * qq.z + k4.w * qq.w;
    }

    // softmax over the 128 sentences
    red[t] = logit; __syncthreads();
#pragma unroll
    for (int o = 64; o > 0; o >>= 1) { if (t < o) red[t] = fmaxf(red[t], red[t + o]); __syncthreads(); }
    float mx = red[0]; __syncthreads();
    float e = expf(logit - mx);
    red[t] = e; __syncthreads();
#pragma unroll
    for (int o = 64; o > 0; o >>= 1) { if (t < o) red[t] += red[t + o]; __syncthreads(); }
    float ssum = red[0]; __syncthreads();
    float attn = e / ssum;

    float v  = g_v[b * NSENT + t];
    float sr = (t == 0) ? v : (v - g_v[b * NSENT + t - 1]);
    float srw = sr * attn;
    out[b * NSENT + t] = srw;

    red[t] = srw; __syncthreads();
#pragma unroll
    for (int o = 64; o > 0; o >>= 1) { if (t < o) red[t] += red[t + o]; __syncthreads(); }
    if (t == 0) out[BATCH * NSENT + b] = red[0];
}

// ---------------- host launcher ----------------
extern "C" void kernel_launch(void* const* d_in, const int* in_sizes, int n_in,
                              void* d_out, int out_size) {
    const float* hidden = (const float*)d_in[0];
    const int*   mask   = (const int*)d_in[1];
    int off = (n_in > 2 && in_sizes[2] == 1) ? 3 : 2;
    const float* Wq = (const float*)d_in[off + 0];
    const float* bq = (const float*)d_in[off + 1];
    const float* Wk = (const float*)d_in[off + 2];
    const float* bk = (const float*)d_in[off + 3];
    const float* Wr = (const float*)d_in[off + 4];
    const float* br = (const float*)d_in[off + 5];
    float* out = (float*)d_out;

    cudaFuncSetAttribute(mma_kernel, cudaFuncAttributeMaxDynamicSharedMemorySize,
                         MMA_SMEM_TOTAL);

    prepw_kernel<<<DDIM * HDIM / 4 / 256, 256>>>(Wk);
    idx_kernel<<<BATCH, 32>>>(mask);
    mma_kernel<<<dim3(KS2, BATCH), 256, MMA_SMEM_TOTAL>>>(hidden);
    qv_kernel<<<(2 * BATCH * NSENT) / 4, 128>>>(hidden, Wq, bq, Wr, br);
    kred_kernel<<<(BATCH * NSENT * 64 + 255) / 256, 256>>>(bk);
    finalize_kernel<<<BATCH, 128>>>(out);
    (void)in_sizes; (void)n_in; (void)out_size;
}